// round 5
// baseline (speedup 1.0000x reference)
#include <cuda_runtime.h>

#define BATCH   4096
#define FEAT    40960
#define ACCUM   512
#define H1      32
#define MAXIDX  128

// Scratch (device globals — no allocations allowed)
__device__ float g_ftT[(size_t)FEAT * ACCUM];   // transposed ft weights [FEAT][ACCUM]
__device__ int   g_stm_mode;                    // 0 = byte bool, 1 = int32, 2 = float32

// ---------------------------------------------------------------------------
// K0: detect stm dtype (reads only first 4096 bytes — safe under all layouts).
// ---------------------------------------------------------------------------
__global__ void k0_prep(const unsigned char* __restrict__ stm) {
    __shared__ int bad_int, bad_f32;
    if (threadIdx.x == 0) { bad_int = 0; bad_f32 = 0; }
    __syncthreads();
    for (int g = threadIdx.x; g < 1024; g += blockDim.x) {
        unsigned char b0 = stm[4*g+0], b1 = stm[4*g+1];
        unsigned char b2 = stm[4*g+2], b3 = stm[4*g+3];
        if (!((b1 | b2 | b3) == 0 && b0 <= 1)) atomicOr(&bad_int, 1);
        bool zero = (b0 | b1 | b2 | b3) == 0;
        bool one  = (b0 == 0 && b1 == 0 && b2 == 0x80 && b3 == 0x3F);
        if (!(zero || one)) atomicOr(&bad_f32, 1);
    }
    __syncthreads();
    if (threadIdx.x == 0)
        g_stm_mode = (!bad_int) ? 1 : ((!bad_f32) ? 2 : 0);
}

// ---------------------------------------------------------------------------
// K1: transpose ft_w [ACCUM, FEAT] -> g_ftT [FEAT, ACCUM] (tiled 32x32).
// ---------------------------------------------------------------------------
__global__ void transpose_kernel(const float* __restrict__ ftw) {
    __shared__ float tile[32][33];
    int fx = blockIdx.x * 32;
    int oy = blockIdx.y * 32;
    int tx = threadIdx.x, ty = threadIdx.y;   // block (32, 8)
    #pragma unroll
    for (int j = 0; j < 32; j += 8)
        tile[ty + j][tx] = ftw[(size_t)(oy + ty + j) * FEAT + (fx + tx)];
    __syncthreads();
    #pragma unroll
    for (int j = 0; j < 32; j += 8)
        g_ftT[(size_t)(fx + ty + j) * ACCUM + (oy + tx)] = tile[tx][ty + j];
}

// ---------------------------------------------------------------------------
// Slow path: emit indices of nonzero elements (values are bit-exact 0.0/1.0,
// so a bitwise test is exact). Marked noinline-ish cold via rarely-taken if.
// ---------------------------------------------------------------------------
__device__ __forceinline__ void emit4(uint4 v, int base, int* cnt, int* idx) {
    if (v.x) { int p = atomicAdd(cnt, 1); if (p < MAXIDX) idx[p] = base + 0; }
    if (v.y) { int p = atomicAdd(cnt, 1); if (p < MAXIDX) idx[p] = base + 1; }
    if (v.z) { int p = atomicAdd(cnt, 1); if (p < MAXIDX) idx[p] = base + 2; }
    if (v.w) { int p = atomicAdd(cnt, 1); if (p < MAXIDX) idx[p] = base + 3; }
}

// ---------------------------------------------------------------------------
// K2: NNUE forward. One block per batch row, 512 threads.
// Scan: rolled loop, unroll 2 -> 4 independent 16B loads in flight,
// ~6 instructions per 16B via bitwise zero fast-path (issue-bound fix).
// ---------------------------------------------------------------------------
__global__ __launch_bounds__(512, 2) void nnue_kernel(
    const float* __restrict__ wf, const float* __restrict__ bf,
    const unsigned char* __restrict__ stm_raw,
    const float* __restrict__ ft_b,
    const float* __restrict__ l1_w, const float* __restrict__ l1_b,
    const float* __restrict__ l2_w, const float* __restrict__ l2_b,
    const float* __restrict__ out_w, const float* __restrict__ out_b,
    float* __restrict__ out)
{
    const int row = blockIdx.x;
    const int t   = threadIdx.x;

    __shared__ int   idxw[MAXIDX], idxb[MAXIDX];
    __shared__ int   nw, nb;
    __shared__ float x[2 * ACCUM];
    __shared__ float v1s[H1];

    if (t == 0) { nw = 0; nb = 0; }
    __syncthreads();

    // ---- Phase A: scan ----
    const uint4* wrow = (const uint4*)(wf + (size_t)row * FEAT);
    const uint4* brow = (const uint4*)(bf + (size_t)row * FEAT);
    #pragma unroll 2
    for (int i = 0; i < FEAT / 4 / 512; i++) {    // 20 iterations
        int vi = t + i * 512;
        uint4 v = wrow[vi];
        uint4 u = brow[vi];
        unsigned nzv = v.x | v.y | v.z | v.w;
        unsigned nzu = u.x | u.y | u.z | u.w;
        if (nzv) emit4(v, 4 * vi, &nw, idxw);
        if (nzu) emit4(u, 4 * vi, &nb, idxb);
    }
    __syncthreads();

    const int cw = min(nw, MAXIDX), cb = min(nb, MAXIDX);

    // ---- Phase B: accumulate, 8-deep load window (rolled loop) ----
    float accw;
    {
        float a0=0.f,a1=0.f,a2=0.f,a3=0.f,a4=0.f,a5=0.f,a6=0.f,a7=0.f;
        int k = 0;
        #pragma unroll 1
        for (; k + 8 <= cw; k += 8) {
            a0 += g_ftT[(size_t)idxw[k+0] * ACCUM + t];
            a1 += g_ftT[(size_t)idxw[k+1] * ACCUM + t];
            a2 += g_ftT[(size_t)idxw[k+2] * ACCUM + t];
            a3 += g_ftT[(size_t)idxw[k+3] * ACCUM + t];
            a4 += g_ftT[(size_t)idxw[k+4] * ACCUM + t];
            a5 += g_ftT[(size_t)idxw[k+5] * ACCUM + t];
            a6 += g_ftT[(size_t)idxw[k+6] * ACCUM + t];
            a7 += g_ftT[(size_t)idxw[k+7] * ACCUM + t];
        }
        for (; k < cw; k++) a0 += g_ftT[(size_t)idxw[k] * ACCUM + t];
        accw = ft_b[t] + ((a0+a1)+(a2+a3)) + ((a4+a5)+(a6+a7));
    }
    float accb;
    {
        float a0=0.f,a1=0.f,a2=0.f,a3=0.f,a4=0.f,a5=0.f,a6=0.f,a7=0.f;
        int k = 0;
        #pragma unroll 1
        for (; k + 8 <= cb; k += 8) {
            a0 += g_ftT[(size_t)idxb[k+0] * ACCUM + t];
            a1 += g_ftT[(size_t)idxb[k+1] * ACCUM + t];
            a2 += g_ftT[(size_t)idxb[k+2] * ACCUM + t];
            a3 += g_ftT[(size_t)idxb[k+3] * ACCUM + t];
            a4 += g_ftT[(size_t)idxb[k+4] * ACCUM + t];
            a5 += g_ftT[(size_t)idxb[k+5] * ACCUM + t];
            a6 += g_ftT[(size_t)idxb[k+6] * ACCUM + t];
            a7 += g_ftT[(size_t)idxb[k+7] * ACCUM + t];
        }
        for (; k < cb; k++) a0 += g_ftT[(size_t)idxb[k] * ACCUM + t];
        accb = ft_b[t] + ((a0+a1)+(a2+a3)) + ((a4+a5)+(a6+a7));
    }

    // screlu
    accw = fminf(fmaxf(accw, 0.f), 1.f); accw *= accw;
    accb = fminf(fmaxf(accb, 0.f), 1.f); accb *= accb;

    // stm select
    bool s;
    {
        int mode = g_stm_mode;
        if (mode == 1)      s = ((const int*)stm_raw)[row] != 0;
        else if (mode == 2) s = ((const float*)stm_raw)[row] != 0.f;
        else                s = stm_raw[row] != 0;
    }
    x[t]         = s ? accb : accw;
    x[ACCUM + t] = s ? accw : accb;
    __syncthreads();

    // ---- Phase C: L1 (32 outputs x 1024 dot), 16 warps x 2 outputs ----
    const int warp = t >> 5, lane = t & 31;
    #pragma unroll
    for (int oo = 0; oo < 2; oo++) {
        int o = warp * 2 + oo;
        const float* w1 = l1_w + (size_t)o * (2 * ACCUM);
        float sum = 0.f;
        #pragma unroll
        for (int j = lane; j < 2 * ACCUM; j += 32)
            sum += x[j] * __ldg(&w1[j]);
        #pragma unroll
        for (int off = 16; off > 0; off >>= 1)
            sum += __shfl_down_sync(0xffffffffu, sum, off);
        if (lane == 0) {
            sum += l1_b[o];
            sum = fminf(fmaxf(sum, 0.f), 1.f);
            v1s[o] = sum * sum;
        }
    }
    __syncthreads();

    // ---- L2 layer + output head (warp 0) ----
    if (warp == 0) {
        float sum = l2_b[lane];
        #pragma unroll
        for (int j = 0; j < H1; j++)
            sum += v1s[j] * __ldg(&l2_w[lane * H1 + j]);
        sum = fminf(fmaxf(sum, 0.f), 1.f);
        float vv = sum * sum * __ldg(&out_w[lane]);
        #pragma unroll
        for (int off = 16; off > 0; off >>= 1)
            vv += __shfl_down_sync(0xffffffffu, vv, off);
        if (lane == 0) out[row] = vv + out_b[0];
    }
}

// ---------------------------------------------------------------------------
extern "C" void kernel_launch(void* const* d_in, const int* in_sizes, int n_in,
                              void* d_out, int out_size) {
    const float*         wf    = (const float*)d_in[0];
    const float*         bf    = (const float*)d_in[1];
    const unsigned char* stm   = (const unsigned char*)d_in[2];
    const float*         ft_w  = (const float*)d_in[3];
    const float*         ft_b  = (const float*)d_in[4];
    const float*         l1_w  = (const float*)d_in[5];
    const float*         l1_b  = (const float*)d_in[6];
    const float*         l2_w  = (const float*)d_in[7];
    const float*         l2_b  = (const float*)d_in[8];
    const float*         out_w = (const float*)d_in[9];
    const float*         out_b = (const float*)d_in[10];
    float*               out   = (float*)d_out;

    k0_prep<<<1, 256>>>(stm);

    dim3 tgrid(FEAT / 32, ACCUM / 32);
    dim3 tblock(32, 8);
    transpose_kernel<<<tgrid, tblock>>>(ft_w);

    nnue_kernel<<<BATCH, 512>>>(wf, bf, stm, ft_b, l1_w, l1_b,
                                l2_w, l2_b, out_w, out_b, out);
}

// round 6
// speedup vs baseline: 1.1877x; 1.1877x over previous
#include <cuda_runtime.h>

#define BATCH   4096
#define FEAT    40960
#define ACCUM   512
#define H1      32
#define MAXIDX  128

// Scratch (device globals — no allocations allowed)
__device__ float g_ftT[(size_t)FEAT * ACCUM];   // transposed ft weights [FEAT][ACCUM]
__device__ int   g_stm_mode;                    // 0 = byte bool, 1 = int32, 2 = float32

// ---------------------------------------------------------------------------
// K1: transpose ft_w [ACCUM, FEAT] -> g_ftT [FEAT, ACCUM] (tiled 32x32).
// Block (0,0) additionally detects the stm dtype (reads only the first 4096
// bytes — safe under byte-bool / int32 / float32 layouts alike).
// ---------------------------------------------------------------------------
__global__ void transpose_kernel(const float* __restrict__ ftw,
                                 const unsigned char* __restrict__ stm) {
    __shared__ float tile[32][33];
    __shared__ int bad_int, bad_f32;

    const int t = threadIdx.y * 32 + threadIdx.x;   // 0..255
    const bool detect = (blockIdx.x == 0 && blockIdx.y == 0);

    if (detect) {
        if (t == 0) { bad_int = 0; bad_f32 = 0; }
        __syncthreads();
        for (int g = t; g < 1024; g += 256) {
            unsigned char b0 = stm[4*g+0], b1 = stm[4*g+1];
            unsigned char b2 = stm[4*g+2], b3 = stm[4*g+3];
            if (!((b1 | b2 | b3) == 0 && b0 <= 1)) atomicOr(&bad_int, 1);
            bool zero = (b0 | b1 | b2 | b3) == 0;
            bool one  = (b0 == 0 && b1 == 0 && b2 == 0x80 && b3 == 0x3F);
            if (!(zero || one)) atomicOr(&bad_f32, 1);
        }
        __syncthreads();
        if (t == 0)
            g_stm_mode = (!bad_int) ? 1 : ((!bad_f32) ? 2 : 0);
        __syncthreads();
    }

    int fx = blockIdx.x * 32;
    int oy = blockIdx.y * 32;
    int tx = threadIdx.x, ty = threadIdx.y;   // block (32, 8)
    #pragma unroll
    for (int j = 0; j < 32; j += 8)
        tile[ty + j][tx] = ftw[(size_t)(oy + ty + j) * FEAT + (fx + tx)];
    __syncthreads();
    #pragma unroll
    for (int j = 0; j < 32; j += 8)
        g_ftT[(size_t)(fx + ty + j) * ACCUM + (oy + tx)] = tile[tx][ty + j];
}

// ---------------------------------------------------------------------------
// K2: NNUE forward. One block per batch row, 512 threads, 3 CTAs/SM target
// (48 warps/SM) so enough loads are in flight to cover DRAM latency.
// Scan identical to the proven R1 version (float4, full unroll, predicated
// emits — ptxas front-batches loads for high MLP_eff).
// ---------------------------------------------------------------------------
__global__ __launch_bounds__(512, 3) void nnue_kernel(
    const float* __restrict__ wf, const float* __restrict__ bf,
    const unsigned char* __restrict__ stm_raw,
    const float* __restrict__ ft_b,
    const float* __restrict__ l1_w, const float* __restrict__ l1_b,
    const float* __restrict__ l2_w, const float* __restrict__ l2_b,
    const float* __restrict__ out_w, const float* __restrict__ out_b,
    float* __restrict__ out)
{
    const int row = blockIdx.x;
    const int t   = threadIdx.x;

    __shared__ int   idxw[MAXIDX], idxb[MAXIDX];
    __shared__ int   nw, nb;
    __shared__ float x[2 * ACCUM];
    __shared__ float v1s[H1];

    if (t == 0) { nw = 0; nb = 0; }
    __syncthreads();

    // ---- Phase A: scan features (vectorized), gather active indices ----
    const float4* wrow = (const float4*)(wf + (size_t)row * FEAT);
    const float4* brow = (const float4*)(bf + (size_t)row * FEAT);
    #pragma unroll
    for (int i = 0; i < FEAT / 4 / 512; i++) {   // 20 iterations
        int vi = t + i * 512;
        float4 v = wrow[vi];
        if (v.x != 0.f) { int p = atomicAdd(&nw, 1); if (p < MAXIDX) idxw[p] = 4*vi + 0; }
        if (v.y != 0.f) { int p = atomicAdd(&nw, 1); if (p < MAXIDX) idxw[p] = 4*vi + 1; }
        if (v.z != 0.f) { int p = atomicAdd(&nw, 1); if (p < MAXIDX) idxw[p] = 4*vi + 2; }
        if (v.w != 0.f) { int p = atomicAdd(&nw, 1); if (p < MAXIDX) idxw[p] = 4*vi + 3; }
        float4 u = brow[vi];
        if (u.x != 0.f) { int p = atomicAdd(&nb, 1); if (p < MAXIDX) idxb[p] = 4*vi + 0; }
        if (u.y != 0.f) { int p = atomicAdd(&nb, 1); if (p < MAXIDX) idxb[p] = 4*vi + 1; }
        if (u.z != 0.f) { int p = atomicAdd(&nb, 1); if (p < MAXIDX) idxb[p] = 4*vi + 2; }
        if (u.w != 0.f) { int p = atomicAdd(&nb, 1); if (p < MAXIDX) idxb[p] = 4*vi + 3; }
    }
    __syncthreads();

    const int cw = min(nw, MAXIDX), cb = min(nb, MAXIDX);

    // ---- Phase B: accumulate (4-way ILP, rolled to bound reg pressure) ----
    float a0 = 0.f, a1 = 0.f, a2 = 0.f, a3 = 0.f;
    int k = 0;
    #pragma unroll 1
    for (; k + 4 <= cw; k += 4) {
        a0 += g_ftT[(size_t)idxw[k+0] * ACCUM + t];
        a1 += g_ftT[(size_t)idxw[k+1] * ACCUM + t];
        a2 += g_ftT[(size_t)idxw[k+2] * ACCUM + t];
        a3 += g_ftT[(size_t)idxw[k+3] * ACCUM + t];
    }
    for (; k < cw; k++) a0 += g_ftT[(size_t)idxw[k] * ACCUM + t];
    float accw = ft_b[t] + (a0 + a1) + (a2 + a3);

    float b0 = 0.f, b1 = 0.f, b2 = 0.f, b3 = 0.f;
    k = 0;
    #pragma unroll 1
    for (; k + 4 <= cb; k += 4) {
        b0 += g_ftT[(size_t)idxb[k+0] * ACCUM + t];
        b1 += g_ftT[(size_t)idxb[k+1] * ACCUM + t];
        b2 += g_ftT[(size_t)idxb[k+2] * ACCUM + t];
        b3 += g_ftT[(size_t)idxb[k+3] * ACCUM + t];
    }
    for (; k < cb; k++) b0 += g_ftT[(size_t)idxb[k] * ACCUM + t];
    float accb = ft_b[t] + (b0 + b1) + (b2 + b3);

    // screlu
    accw = fminf(fmaxf(accw, 0.f), 1.f); accw *= accw;
    accb = fminf(fmaxf(accb, 0.f), 1.f); accb *= accb;

    // stm select (dtype-mode decoded)
    bool s;
    {
        int mode = g_stm_mode;
        if (mode == 1)      s = ((const int*)stm_raw)[row] != 0;
        else if (mode == 2) s = ((const float*)stm_raw)[row] != 0.f;
        else                s = stm_raw[row] != 0;
    }
    x[t]         = s ? accb : accw;
    x[ACCUM + t] = s ? accw : accb;
    __syncthreads();

    // ---- Phase C: L1 (32 outputs x 1024 dot), 16 warps x 2 outputs ----
    const int warp = t >> 5, lane = t & 31;
    #pragma unroll
    for (int oo = 0; oo < 2; oo++) {
        int o = warp * 2 + oo;
        const float* w1 = l1_w + (size_t)o * (2 * ACCUM);
        float sum = 0.f;
        #pragma unroll
        for (int j = lane; j < 2 * ACCUM; j += 32)
            sum += x[j] * __ldg(&w1[j]);
        #pragma unroll
        for (int off = 16; off > 0; off >>= 1)
            sum += __shfl_down_sync(0xffffffffu, sum, off);
        if (lane == 0) {
            sum += l1_b[o];
            sum = fminf(fmaxf(sum, 0.f), 1.f);
            v1s[o] = sum * sum;
        }
    }
    __syncthreads();

    // ---- L2 layer + output head (warp 0) ----
    if (warp == 0) {
        float sum = l2_b[lane];
        #pragma unroll
        for (int j = 0; j < H1; j++)
            sum += v1s[j] * __ldg(&l2_w[lane * H1 + j]);
        sum = fminf(fmaxf(sum, 0.f), 1.f);
        float vv = sum * sum * __ldg(&out_w[lane]);
        #pragma unroll
        for (int off = 16; off > 0; off >>= 1)
            vv += __shfl_down_sync(0xffffffffu, vv, off);
        if (lane == 0) out[row] = vv + out_b[0];
    }
}

// ---------------------------------------------------------------------------
extern "C" void kernel_launch(void* const* d_in, const int* in_sizes, int n_in,
                              void* d_out, int out_size) {
    const float*         wf    = (const float*)d_in[0];
    const float*         bf    = (const float*)d_in[1];
    const unsigned char* stm   = (const unsigned char*)d_in[2];
    const float*         ft_w  = (const float*)d_in[3];
    const float*         ft_b  = (const float*)d_in[4];
    const float*         l1_w  = (const float*)d_in[5];
    const float*         l1_b  = (const float*)d_in[6];
    const float*         l2_w  = (const float*)d_in[7];
    const float*         l2_b  = (const float*)d_in[8];
    const float*         out_w = (const float*)d_in[9];
    const float*         out_b = (const float*)d_in[10];
    float*               out   = (float*)d_out;

    dim3 tgrid(FEAT / 32, ACCUM / 32);
    dim3 tblock(32, 8);
    transpose_kernel<<<tgrid, tblock>>>(ft_w, stm);

    nnue_kernel<<<BATCH, 512>>>(wf, bf, stm, ft_b, l1_w, l1_b,
                                l2_w, l2_b, out_w, out_b, out);
}

// round 7
// speedup vs baseline: 1.2482x; 1.0509x over previous
#include <cuda_runtime.h>

#define BATCH   4096
#define FEAT    40960
#define ACCUM   512
#define H1      32
#define MAXIDX  128

// Scratch (device globals — no allocations allowed)
__device__ float g_ftT[(size_t)FEAT * ACCUM];   // transposed ft weights [FEAT][ACCUM]
__device__ int   g_stm_mode;                    // 0 = byte bool, 1 = int32, 2 = float32

// ---------------------------------------------------------------------------
// K1: transpose ft_w [ACCUM, FEAT] -> g_ftT [FEAT, ACCUM] (tiled 32x32).
// Block (0,0) additionally detects the stm dtype (reads only the first 4096
// bytes — safe under byte-bool / int32 / float32 layouts alike).
// ---------------------------------------------------------------------------
__global__ void transpose_kernel(const float* __restrict__ ftw,
                                 const unsigned char* __restrict__ stm) {
    __shared__ float tile[32][33];
    __shared__ int bad_int, bad_f32;

    const int t = threadIdx.y * 32 + threadIdx.x;   // 0..255
    const bool detect = (blockIdx.x == 0 && blockIdx.y == 0);

    if (detect) {
        if (t == 0) { bad_int = 0; bad_f32 = 0; }
        __syncthreads();
        for (int g = t; g < 1024; g += 256) {
            unsigned char b0 = stm[4*g+0], b1 = stm[4*g+1];
            unsigned char b2 = stm[4*g+2], b3 = stm[4*g+3];
            if (!((b1 | b2 | b3) == 0 && b0 <= 1)) atomicOr(&bad_int, 1);
            bool zero = (b0 | b1 | b2 | b3) == 0;
            bool one  = (b0 == 0 && b1 == 0 && b2 == 0x80 && b3 == 0x3F);
            if (!(zero || one)) atomicOr(&bad_f32, 1);
        }
        __syncthreads();
        if (t == 0)
            g_stm_mode = (!bad_int) ? 1 : ((!bad_f32) ? 2 : 0);
        __syncthreads();
    }

    int fx = blockIdx.x * 32;
    int oy = blockIdx.y * 32;
    int tx = threadIdx.x, ty = threadIdx.y;   // block (32, 8)
    #pragma unroll
    for (int j = 0; j < 32; j += 8)
        tile[ty + j][tx] = ftw[(size_t)(oy + ty + j) * FEAT + (fx + tx)];
    __syncthreads();
    #pragma unroll
    for (int j = 0; j < 32; j += 8)
        g_ftT[(size_t)(fx + ty + j) * ACCUM + (oy + tx)] = tile[tx][ty + j];
}

// ---------------------------------------------------------------------------
// K2: NNUE forward. One block per batch row, 512 threads.
// launch_bounds(512,4): 32 regs/thread -> 4 CTAs/SM = 64 warps (full occ).
// Scan split into two sequential passes (white, black) so the live float4
// window per loop fits the 32-reg budget without spilling.
// ---------------------------------------------------------------------------
__global__ __launch_bounds__(512, 4) void nnue_kernel(
    const float* __restrict__ wf, const float* __restrict__ bf,
    const unsigned char* __restrict__ stm_raw,
    const float* __restrict__ ft_b,
    const float* __restrict__ l1_w, const float* __restrict__ l1_b,
    const float* __restrict__ l2_w, const float* __restrict__ l2_b,
    const float* __restrict__ out_w, const float* __restrict__ out_b,
    float* __restrict__ out)
{
    const int row = blockIdx.x;
    const int t   = threadIdx.x;

    __shared__ int   idxw[MAXIDX], idxb[MAXIDX];
    __shared__ int   nw, nb;
    __shared__ float x[2 * ACCUM];
    __shared__ float v1s[H1];

    if (t == 0) { nw = 0; nb = 0; }
    __syncthreads();

    // ---- Phase A: scan features — white pass, then black pass ----
    const float4* wrow = (const float4*)(wf + (size_t)row * FEAT);
    const float4* brow = (const float4*)(bf + (size_t)row * FEAT);

    #pragma unroll
    for (int i = 0; i < FEAT / 4 / 512; i++) {   // 20 iterations
        int vi = t + i * 512;
        float4 v = wrow[vi];
        if (v.x != 0.f) { int p = atomicAdd(&nw, 1); if (p < MAXIDX) idxw[p] = 4*vi + 0; }
        if (v.y != 0.f) { int p = atomicAdd(&nw, 1); if (p < MAXIDX) idxw[p] = 4*vi + 1; }
        if (v.z != 0.f) { int p = atomicAdd(&nw, 1); if (p < MAXIDX) idxw[p] = 4*vi + 2; }
        if (v.w != 0.f) { int p = atomicAdd(&nw, 1); if (p < MAXIDX) idxw[p] = 4*vi + 3; }
    }
    #pragma unroll
    for (int i = 0; i < FEAT / 4 / 512; i++) {   // 20 iterations
        int vi = t + i * 512;
        float4 u = brow[vi];
        if (u.x != 0.f) { int p = atomicAdd(&nb, 1); if (p < MAXIDX) idxb[p] = 4*vi + 0; }
        if (u.y != 0.f) { int p = atomicAdd(&nb, 1); if (p < MAXIDX) idxb[p] = 4*vi + 1; }
        if (u.z != 0.f) { int p = atomicAdd(&nb, 1); if (p < MAXIDX) idxb[p] = 4*vi + 2; }
        if (u.w != 0.f) { int p = atomicAdd(&nb, 1); if (p < MAXIDX) idxb[p] = 4*vi + 3; }
    }
    __syncthreads();

    const int cw = min(nw, MAXIDX), cb = min(nb, MAXIDX);

    // ---- Phase B: accumulate (4-way ILP, rolled to bound reg pressure) ----
    float a0 = 0.f, a1 = 0.f, a2 = 0.f, a3 = 0.f;
    int k = 0;
    #pragma unroll 1
    for (; k + 4 <= cw; k += 4) {
        a0 += g_ftT[(size_t)idxw[k+0] * ACCUM + t];
        a1 += g_ftT[(size_t)idxw[k+1] * ACCUM + t];
        a2 += g_ftT[(size_t)idxw[k+2] * ACCUM + t];
        a3 += g_ftT[(size_t)idxw[k+3] * ACCUM + t];
    }
    for (; k < cw; k++) a0 += g_ftT[(size_t)idxw[k] * ACCUM + t];
    float accw = ft_b[t] + (a0 + a1) + (a2 + a3);

    float b0 = 0.f, b1 = 0.f, b2 = 0.f, b3 = 0.f;
    k = 0;
    #pragma unroll 1
    for (; k + 4 <= cb; k += 4) {
        b0 += g_ftT[(size_t)idxb[k+0] * ACCUM + t];
        b1 += g_ftT[(size_t)idxb[k+1] * ACCUM + t];
        b2 += g_ftT[(size_t)idxb[k+2] * ACCUM + t];
        b3 += g_ftT[(size_t)idxb[k+3] * ACCUM + t];
    }
    for (; k < cb; k++) b0 += g_ftT[(size_t)idxb[k] * ACCUM + t];
    float accb = ft_b[t] + (b0 + b1) + (b2 + b3);

    // screlu
    accw = fminf(fmaxf(accw, 0.f), 1.f); accw *= accw;
    accb = fminf(fmaxf(accb, 0.f), 1.f); accb *= accb;

    // stm select (dtype-mode decoded)
    bool s;
    {
        int mode = g_stm_mode;
        if (mode == 1)      s = ((const int*)stm_raw)[row] != 0;
        else if (mode == 2) s = ((const float*)stm_raw)[row] != 0.f;
        else                s = stm_raw[row] != 0;
    }
    x[t]         = s ? accb : accw;
    x[ACCUM + t] = s ? accw : accb;
    __syncthreads();

    // ---- Phase C: L1 (32 outputs x 1024 dot), 16 warps x 2 outputs ----
    const int warp = t >> 5, lane = t & 31;
    #pragma unroll
    for (int oo = 0; oo < 2; oo++) {
        int o = warp * 2 + oo;
        const float* w1 = l1_w + (size_t)o * (2 * ACCUM);
        float sum = 0.f;
        #pragma unroll
        for (int j = lane; j < 2 * ACCUM; j += 32)
            sum += x[j] * __ldg(&w1[j]);
        #pragma unroll
        for (int off = 16; off > 0; off >>= 1)
            sum += __shfl_down_sync(0xffffffffu, sum, off);
        if (lane == 0) {
            sum += l1_b[o];
            sum = fminf(fmaxf(sum, 0.f), 1.f);
            v1s[o] = sum * sum;
        }
    }
    __syncthreads();

    // ---- L2 layer + output head (warp 0) ----
    if (warp == 0) {
        float sum = l2_b[lane];
        #pragma unroll
        for (int j = 0; j < H1; j++)
            sum += v1s[j] * __ldg(&l2_w[lane * H1 + j]);
        sum = fminf(fmaxf(sum, 0.f), 1.f);
        float vv = sum * sum * __ldg(&out_w[lane]);
        #pragma unroll
        for (int off = 16; off > 0; off >>= 1)
            vv += __shfl_down_sync(0xffffffffu, vv, off);
        if (lane == 0) out[row] = vv + out_b[0];
    }
}

// ---------------------------------------------------------------------------
extern "C" void kernel_launch(void* const* d_in, const int* in_sizes, int n_in,
                              void* d_out, int out_size) {
    const float*         wf    = (const float*)d_in[0];
    const float*         bf    = (const float*)d_in[1];
    const unsigned char* stm   = (const unsigned char*)d_in[2];
    const float*         ft_w  = (const float*)d_in[3];
    const float*         ft_b  = (const float*)d_in[4];
    const float*         l1_w  = (const float*)d_in[5];
    const float*         l1_b  = (const float*)d_in[6];
    const float*         l2_w  = (const float*)d_in[7];
    const float*         l2_b  = (const float*)d_in[8];
    const float*         out_w = (const float*)d_in[9];
    const float*         out_b = (const float*)d_in[10];
    float*               out   = (float*)d_out;

    dim3 tgrid(FEAT / 32, ACCUM / 32);
    dim3 tblock(32, 8);
    transpose_kernel<<<tgrid, tblock>>>(ft_w, stm);

    nnue_kernel<<<BATCH, 512>>>(wf, bf, stm, ft_b, l1_w, l1_b,
                                l2_w, l2_b, out_w, out_b, out);
}

// round 9
// speedup vs baseline: 1.3659x; 1.0943x over previous
#include <cuda_runtime.h>

#define BATCH   4096
#define FEAT    40960
#define ACCUM   512
#define H1      32
#define MAXIDX  128

// Scratch (device globals — no allocations allowed)
__device__ float g_ftT[(size_t)FEAT * ACCUM];   // transposed ft weights [FEAT][ACCUM]
__device__ int   g_stm_mode;                    // 0 = byte bool, 1 = int32, 2 = float32

// ---------------------------------------------------------------------------
// K1: transpose ft_w [ACCUM, FEAT] -> g_ftT [FEAT, ACCUM] (tiled 32x32).
// Block (0,0) additionally detects the stm dtype.
// Reads use __ldcs (read-once); writes stay write-allocate so g_ftT lands in L2.
// ---------------------------------------------------------------------------
__global__ void transpose_kernel(const float* __restrict__ ftw,
                                 const unsigned char* __restrict__ stm) {
    __shared__ float tile[32][33];
    __shared__ int bad_int, bad_f32;

    const int t = threadIdx.y * 32 + threadIdx.x;   // 0..255
    const bool detect = (blockIdx.x == 0 && blockIdx.y == 0);

    if (detect) {
        if (t == 0) { bad_int = 0; bad_f32 = 0; }
        __syncthreads();
        for (int g = t; g < 1024; g += 256) {
            unsigned char b0 = stm[4*g+0], b1 = stm[4*g+1];
            unsigned char b2 = stm[4*g+2], b3 = stm[4*g+3];
            if (!((b1 | b2 | b3) == 0 && b0 <= 1)) atomicOr(&bad_int, 1);
            bool zero = (b0 | b1 | b2 | b3) == 0;
            bool one  = (b0 == 0 && b1 == 0 && b2 == 0x80 && b3 == 0x3F);
            if (!(zero || one)) atomicOr(&bad_f32, 1);
        }
        __syncthreads();
        if (t == 0)
            g_stm_mode = (!bad_int) ? 1 : ((!bad_f32) ? 2 : 0);
        __syncthreads();
    }

    int fx = blockIdx.x * 32;
    int oy = blockIdx.y * 32;
    int tx = threadIdx.x, ty = threadIdx.y;   // block (32, 8)
    #pragma unroll
    for (int j = 0; j < 32; j += 8)
        tile[ty + j][tx] = __ldcs(&ftw[(size_t)(oy + ty + j) * FEAT + (fx + tx)]);
    __syncthreads();
    #pragma unroll
    for (int j = 0; j < 32; j += 8)
        g_ftT[(size_t)(fx + ty + j) * ACCUM + (oy + tx)] = tile[tx][ty + j];
}

// ---------------------------------------------------------------------------
// K2: NNUE forward. One block per batch row, 512 threads, 4 CTAs/SM.
// Scan: proven R7 structure + __ldcs so the read-once feature stream does
// not evict L2-resident g_ftT.
// Gather: 4 groups x 128 threads, float4 per thread (channels 4u..4u+3),
// group g takes features k = g, g+4, ... ; partials in a native float4
// shared array (16B-aligned — R8's misalignment fixed here).
// ---------------------------------------------------------------------------
__global__ __launch_bounds__(512, 4) void nnue_kernel(
    const float* __restrict__ wf, const float* __restrict__ bf,
    const unsigned char* __restrict__ stm_raw,
    const float* __restrict__ ft_b,
    const float* __restrict__ l1_w, const float* __restrict__ l1_b,
    const float* __restrict__ l2_w, const float* __restrict__ l2_b,
    const float* __restrict__ out_w, const float* __restrict__ out_b,
    float* __restrict__ out)
{
    const int row = blockIdx.x;
    const int t   = threadIdx.x;

    __shared__ float4 sp[4][ACCUM / 4];    // gather partials, 16B-aligned (8 KB)
    __shared__ int    idxw[MAXIDX], idxb[MAXIDX];
    __shared__ int    nw, nb;
    __shared__ float  x[2 * ACCUM];
    __shared__ float  v1s[H1];

    if (t == 0) { nw = 0; nb = 0; }
    __syncthreads();

    // ---- Phase A: scan features — white pass, then black pass ----
    const float4* wrow = (const float4*)(wf + (size_t)row * FEAT);
    const float4* brow = (const float4*)(bf + (size_t)row * FEAT);

    #pragma unroll
    for (int i = 0; i < FEAT / 4 / 512; i++) {   // 20 iterations
        int vi = t + i * 512;
        float4 v = __ldcs(&wrow[vi]);
        if (v.x != 0.f) { int p = atomicAdd(&nw, 1); if (p < MAXIDX) idxw[p] = 4*vi + 0; }
        if (v.y != 0.f) { int p = atomicAdd(&nw, 1); if (p < MAXIDX) idxw[p] = 4*vi + 1; }
        if (v.z != 0.f) { int p = atomicAdd(&nw, 1); if (p < MAXIDX) idxw[p] = 4*vi + 2; }
        if (v.w != 0.f) { int p = atomicAdd(&nw, 1); if (p < MAXIDX) idxw[p] = 4*vi + 3; }
    }
    #pragma unroll
    for (int i = 0; i < FEAT / 4 / 512; i++) {   // 20 iterations
        int vi = t + i * 512;
        float4 u = __ldcs(&brow[vi]);
        if (u.x != 0.f) { int p = atomicAdd(&nb, 1); if (p < MAXIDX) idxb[p] = 4*vi + 0; }
        if (u.y != 0.f) { int p = atomicAdd(&nb, 1); if (p < MAXIDX) idxb[p] = 4*vi + 1; }
        if (u.z != 0.f) { int p = atomicAdd(&nb, 1); if (p < MAXIDX) idxb[p] = 4*vi + 2; }
        if (u.w != 0.f) { int p = atomicAdd(&nb, 1); if (p < MAXIDX) idxb[p] = 4*vi + 3; }
    }
    __syncthreads();

    const int cw = min(nw, MAXIDX), cb = min(nb, MAXIDX);

    const int g = t >> 7;        // gather group 0..3
    const int u = t & 127;       // channel block: channels 4u..4u+3
    const float* spf = (const float*)sp;     // scalar view: spf[grp*ACCUM + ch]

    // ---- Phase B1: white gather (float4, grouped) ----
    {
        float4 s0 = {0.f,0.f,0.f,0.f}, s1 = {0.f,0.f,0.f,0.f};
        int k = g;
        #pragma unroll 1
        for (; k + 4 < cw; k += 8) {
            float4 va = *(const float4*)&g_ftT[(size_t)idxw[k]     * ACCUM + 4*u];
            float4 vb = *(const float4*)&g_ftT[(size_t)idxw[k + 4] * ACCUM + 4*u];
            s0.x += va.x; s0.y += va.y; s0.z += va.z; s0.w += va.w;
            s1.x += vb.x; s1.y += vb.y; s1.z += vb.z; s1.w += vb.w;
        }
        if (k < cw) {
            float4 va = *(const float4*)&g_ftT[(size_t)idxw[k] * ACCUM + 4*u];
            s0.x += va.x; s0.y += va.y; s0.z += va.z; s0.w += va.w;
        }
        s0.x += s1.x; s0.y += s1.y; s0.z += s1.z; s0.w += s1.w;
        sp[g][u] = s0;
    }
    __syncthreads();
    float accw = ft_b[t] + (spf[0*ACCUM + t] + spf[1*ACCUM + t])
                         + (spf[2*ACCUM + t] + spf[3*ACCUM + t]);
    __syncthreads();

    // ---- Phase B2: black gather ----
    {
        float4 s0 = {0.f,0.f,0.f,0.f}, s1 = {0.f,0.f,0.f,0.f};
        int k = g;
        #pragma unroll 1
        for (; k + 4 < cb; k += 8) {
            float4 va = *(const float4*)&g_ftT[(size_t)idxb[k]     * ACCUM + 4*u];
            float4 vb = *(const float4*)&g_ftT[(size_t)idxb[k + 4] * ACCUM + 4*u];
            s0.x += va.x; s0.y += va.y; s0.z += va.z; s0.w += va.w;
            s1.x += vb.x; s1.y += vb.y; s1.z += vb.z; s1.w += vb.w;
        }
        if (k < cb) {
            float4 va = *(const float4*)&g_ftT[(size_t)idxb[k] * ACCUM + 4*u];
            s0.x += va.x; s0.y += va.y; s0.z += va.z; s0.w += va.w;
        }
        s0.x += s1.x; s0.y += s1.y; s0.z += s1.z; s0.w += s1.w;
        sp[g][u] = s0;
    }
    __syncthreads();
    float accb = ft_b[t] + (spf[0*ACCUM + t] + spf[1*ACCUM + t])
                         + (spf[2*ACCUM + t] + spf[3*ACCUM + t]);

    // screlu
    accw = fminf(fmaxf(accw, 0.f), 1.f); accw *= accw;
    accb = fminf(fmaxf(accb, 0.f), 1.f); accb *= accb;

    // stm select (dtype-mode decoded)
    bool s;
    {
        int mode = g_stm_mode;
        if (mode == 1)      s = ((const int*)stm_raw)[row] != 0;
        else if (mode == 2) s = ((const float*)stm_raw)[row] != 0.f;
        else                s = stm_raw[row] != 0;
    }
    x[t]         = s ? accb : accw;
    x[ACCUM + t] = s ? accw : accb;
    __syncthreads();

    // ---- Phase C: L1 (32 outputs x 1024 dot), 16 warps x 2 outputs ----
    const int warp = t >> 5, lane = t & 31;
    #pragma unroll
    for (int oo = 0; oo < 2; oo++) {
        int o = warp * 2 + oo;
        const float* w1 = l1_w + (size_t)o * (2 * ACCUM);
        float sum = 0.f;
        #pragma unroll
        for (int j = lane; j < 2 * ACCUM; j += 32)
            sum += x[j] * __ldg(&w1[j]);
        #pragma unroll
        for (int off = 16; off > 0; off >>= 1)
            sum += __shfl_down_sync(0xffffffffu, sum, off);
        if (lane == 0) {
            sum += l1_b[o];
            sum = fminf(fmaxf(sum, 0.f), 1.f);
            v1s[o] = sum * sum;
        }
    }
    __syncthreads();

    // ---- L2 layer + output head (warp 0) ----
    if (warp == 0) {
        float sum = l2_b[lane];
        #pragma unroll
        for (int j = 0; j < H1; j++)
            sum += v1s[j] * __ldg(&l2_w[lane * H1 + j]);
        sum = fminf(fmaxf(sum, 0.f), 1.f);
        float vv = sum * sum * __ldg(&out_w[lane]);
        #pragma unroll
        for (int off = 16; off > 0; off >>= 1)
            vv += __shfl_down_sync(0xffffffffu, vv, off);
        if (lane == 0) out[row] = vv + out_b[0];
    }
}

// ---------------------------------------------------------------------------
extern "C" void kernel_launch(void* const* d_in, const int* in_sizes, int n_in,
                              void* d_out, int out_size) {
    const float*         wf    = (const float*)d_in[0];
    const float*         bf    = (const float*)d_in[1];
    const unsigned char* stm   = (const unsigned char*)d_in[2];
    const float*         ft_w  = (const float*)d_in[3];
    const float*         ft_b  = (const float*)d_in[4];
    const float*         l1_w  = (const float*)d_in[5];
    const float*         l1_b  = (const float*)d_in[6];
    const float*         l2_w  = (const float*)d_in[7];
    const float*         l2_b  = (const float*)d_in[8];
    const float*         out_w = (const float*)d_in[9];
    const float*         out_b = (const float*)d_in[10];
    float*               out   = (float*)d_out;

    dim3 tgrid(FEAT / 32, ACCUM / 32);
    dim3 tblock(32, 8);
    transpose_kernel<<<tgrid, tblock>>>(ft_w, stm);

    nnue_kernel<<<BATCH, 512>>>(wf, bf, stm, ft_b, l1_w, l1_b,
                                l2_w, l2_b, out_w, out_b, out);
}